// round 4
// baseline (speedup 1.0000x reference)
#include <cuda_runtime.h>
#include <cuda_bf16.h>
#include <math.h>

#define BB 16384
#define LL 32

typedef unsigned long long ull;

// scratch (no allocation allowed)
__device__ float g_z[BB * 8];
__device__ float g_T10[BB];

__device__ __forceinline__ ull pack2(float lo, float hi) {
    ull r; asm("mov.b64 %0,{%1,%2};" : "=l"(r) : "f"(lo), "f"(hi)); return r;
}
__device__ __forceinline__ void unpack2(ull v, float& lo, float& hi) {
    asm("mov.b64 {%0,%1},%2;" : "=f"(lo), "=f"(hi) : "l"(v));
}
__device__ __forceinline__ ull fma2(ull a, ull b, ull c) {
    ull d; asm("fma.rn.f32x2 %0,%1,%2,%3;" : "=l"(d) : "l"(a), "l"(b), "l"(c)); return d;
}
__device__ __forceinline__ ull add2(ull a, ull b) {
    ull d; asm("add.rn.f32x2 %0,%1,%2;" : "=l"(d) : "l"(a), "l"(b)); return d;
}

__device__ __forceinline__ float tanh_fast(float x) {
    float e = __expf(2.0f * x);
    return 1.0f - __fdividef(2.0f, e + 1.0f);
}

__device__ __forceinline__ float2 dxval(float s, float2 x0, float2 x1, float2 m0, float2 m1) {
    float s2 = s * s;
    float cx0 = 6.f * s2 - 6.f * s;
    float cm0 = 3.f * s2 - 4.f * s + 1.f;
    float cx1 = -6.f * s2 + 6.f * s;
    float cm1 = 3.f * s2 - 2.f * s;
    float2 r;
    r.x = cx0 * x0.x + cm0 * m0.x + cx1 * x1.x + cm1 * m1.x;
    r.y = cx0 * x0.y + cm0 * m0.y + cx1 * x1.y + cm1 * m1.y;
    return r;
}

// F(s,z) for TWO rows per lane. 4 lanes per row split k (g = lane&3);
// weight loads are shared across both rows and broadcast across the warp.
__device__ __forceinline__ void Feval2(const ull* zA, const ull* zB,
                                       float2 dA, float2 dB,
                                       const float* sW1, const float* sW2T,
                                       const ull* sB1p, const float* sB2,
                                       int g, ull* kA, ull* kB) {
    ull aA[8], aB[8];
#pragma unroll
    for (int j = 0; j < 8; j++) { aA[j] = 0ull; aB[j] = 0ull; }

#pragma unroll 2
    for (int kk = g; kk < 256; kk += 4) {
        ulonglong2 w1a = *reinterpret_cast<const ulonglong2*>(sW1 + kk * 8);
        ulonglong2 w1b = *reinterpret_cast<const ulonglong2*>(sW1 + kk * 8 + 4);
        ull bk = sB1p[kk];

        ull accA = fma2(w1a.x, zA[0], bk);
        ull accB = fma2(w1a.x, zB[0], bk);
        accA = fma2(w1a.y, zA[1], accA);
        accB = fma2(w1a.y, zB[1], accB);
        accA = fma2(w1b.x, zA[2], accA);
        accB = fma2(w1b.x, zB[2], accB);
        accA = fma2(w1b.y, zA[3], accA);
        accB = fma2(w1b.y, zB[3], accB);
        float alo, ahi, blo, bhi;
        unpack2(accA, alo, ahi);
        unpack2(accB, blo, bhi);
        float hA = fmaxf(alo + ahi, 0.f);
        float hB = fmaxf(blo + bhi, 0.f);
        ull hhA = pack2(hA, hA);
        ull hhB = pack2(hB, hB);

        ulonglong2 c0 = *reinterpret_cast<const ulonglong2*>(sW2T + kk * 16);
        ulonglong2 c1 = *reinterpret_cast<const ulonglong2*>(sW2T + kk * 16 + 4);
        ulonglong2 c2 = *reinterpret_cast<const ulonglong2*>(sW2T + kk * 16 + 8);
        ulonglong2 c3 = *reinterpret_cast<const ulonglong2*>(sW2T + kk * 16 + 12);
        aA[0] = fma2(c0.x, hhA, aA[0]);  aB[0] = fma2(c0.x, hhB, aB[0]);
        aA[1] = fma2(c0.y, hhA, aA[1]);  aB[1] = fma2(c0.y, hhB, aB[1]);
        aA[2] = fma2(c1.x, hhA, aA[2]);  aB[2] = fma2(c1.x, hhB, aB[2]);
        aA[3] = fma2(c1.y, hhA, aA[3]);  aB[3] = fma2(c1.y, hhB, aB[3]);
        aA[4] = fma2(c2.x, hhA, aA[4]);  aB[4] = fma2(c2.x, hhB, aB[4]);
        aA[5] = fma2(c2.y, hhA, aA[5]);  aB[5] = fma2(c2.y, hhB, aB[5]);
        aA[6] = fma2(c3.x, hhA, aA[6]);  aB[6] = fma2(c3.x, hhB, aB[6]);
        aA[7] = fma2(c3.y, hhA, aA[7]);  aB[7] = fma2(c3.y, hhB, aB[7]);
    }
    float avA[16], avB[16];
#pragma unroll
    for (int j = 0; j < 8; j++) {
        unpack2(aA[j], avA[2 * j], avA[2 * j + 1]);
        unpack2(aB[j], avB[2 * j], avB[2 * j + 1]);
    }
    // reduce across the 4 parity lanes (same rl)
#pragma unroll
    for (int j = 0; j < 16; j++) {
        avA[j] += __shfl_xor_sync(0xffffffffu, avA[j], 1);
        avB[j] += __shfl_xor_sync(0xffffffffu, avB[j], 1);
        avA[j] += __shfl_xor_sync(0xffffffffu, avA[j], 2);
        avB[j] += __shfl_xor_sync(0xffffffffu, avB[j], 2);
    }

#pragma unroll
    for (int hh = 0; hh < 4; hh++) {
        float a0 = tanh_fast(avA[4 * hh]     + sB2[4 * hh]);
        float a1 = tanh_fast(avA[4 * hh + 1] + sB2[4 * hh + 1]);
        float a2 = tanh_fast(avA[4 * hh + 2] + sB2[4 * hh + 2]);
        float a3 = tanh_fast(avA[4 * hh + 3] + sB2[4 * hh + 3]);
        kA[hh] = pack2(a0 * dA.x + a1 * dA.y, a2 * dA.x + a3 * dA.y);
        float b0 = tanh_fast(avB[4 * hh]     + sB2[4 * hh]);
        float b1 = tanh_fast(avB[4 * hh + 1] + sB2[4 * hh + 1]);
        float b2 = tanh_fast(avB[4 * hh + 2] + sB2[4 * hh + 2]);
        float b3 = tanh_fast(avB[4 * hh + 3] + sB2[4 * hh + 3]);
        kB[hh] = pack2(b0 * dB.x + b1 * dB.y, b2 * dB.x + b3 * dB.y);
    }
}

__device__ __forceinline__ void substep2(ull* zA, ull* zB,
                                         float2 xaA, float2 xbA, float2 m0A, float2 m1A,
                                         float2 xaB, float2 xbB, float2 m0B, float2 m1B,
                                         float s0,
                                         const float* sW1, const float* sW2T,
                                         const ull* sB1p, const float* sB2, int g) {
    float2 dA1 = dxval(s0,         xaA, xbA, m0A, m1A);
    float2 dA2 = dxval(s0 + 0.25f, xaA, xbA, m0A, m1A);
    float2 dA3 = dxval(s0 + 0.5f,  xaA, xbA, m0A, m1A);
    float2 dB1 = dxval(s0,         xaB, xbB, m0B, m1B);
    float2 dB2 = dxval(s0 + 0.25f, xaB, xbB, m0B, m1B);
    float2 dB3 = dxval(s0 + 0.5f,  xaB, xbB, m0B, m1B);

    const ull C025 = pack2(0.25f, 0.25f);
    const ull C05  = pack2(0.5f, 0.5f);
    const ull C2   = pack2(2.f, 2.f);
    const ull C112 = pack2(1.f / 12.f, 1.f / 12.f);

    ull kcA[4], kcB[4], ksA[4], ksB[4], ztA[4], ztB[4];
    Feval2(zA, zB, dA1, dB1, sW1, sW2T, sB1p, sB2, g, kcA, kcB); // k1
#pragma unroll
    for (int j = 0; j < 4; j++) {
        ksA[j] = kcA[j]; ztA[j] = fma2(C025, kcA[j], zA[j]);
        ksB[j] = kcB[j]; ztB[j] = fma2(C025, kcB[j], zB[j]);
    }
    Feval2(ztA, ztB, dA2, dB2, sW1, sW2T, sB1p, sB2, g, kcA, kcB); // k2
#pragma unroll
    for (int j = 0; j < 4; j++) {
        ksA[j] = fma2(C2, kcA[j], ksA[j]); ztA[j] = fma2(C025, kcA[j], zA[j]);
        ksB[j] = fma2(C2, kcB[j], ksB[j]); ztB[j] = fma2(C025, kcB[j], zB[j]);
    }
    Feval2(ztA, ztB, dA2, dB2, sW1, sW2T, sB1p, sB2, g, kcA, kcB); // k3
#pragma unroll
    for (int j = 0; j < 4; j++) {
        ksA[j] = fma2(C2, kcA[j], ksA[j]); ztA[j] = fma2(C05, kcA[j], zA[j]);
        ksB[j] = fma2(C2, kcB[j], ksB[j]); ztB[j] = fma2(C05, kcB[j], zB[j]);
    }
    Feval2(ztA, ztB, dA3, dB3, sW1, sW2T, sB1p, sB2, g, kcA, kcB); // k4
#pragma unroll
    for (int j = 0; j < 4; j++) {
        zA[j] = fma2(C112, add2(ksA[j], kcA[j]), zA[j]);
        zB[j] = fma2(C112, add2(ksB[j], kcB[j]), zB[j]);
    }
}

__global__ void __launch_bounds__(32, 8)
k1_ode(const float* __restrict__ X_in, const float* __restrict__ fa_in,
       const int* __restrict__ fa_len,
       const float* __restrict__ W_init, const float* __restrict__ b_init,
       const float* __restrict__ W1, const float* __restrict__ b1,
       const float* __restrict__ W2, const float* __restrict__ b2) {
    __shared__ __align__(16) float sW1[256 * 8];
    __shared__ __align__(16) float sW2T[256 * 16];
    __shared__ __align__(16) ull   sB1p[256];   // (b1, 0) packed
    __shared__ float sB2[16];
    __shared__ float sWI[16];
    __shared__ float sBI[8];
    __shared__ float2 sX[16][33];

    int tid = threadIdx.x;   // 0..31
    for (int i = tid; i < 256 * 8; i += 32) sW1[i] = W1[i];
    for (int i = tid; i < 16 * 256; i += 32) {
        int j = i >> 8;    // 0..15
        int k = i & 255;   // 0..255
        sW2T[k * 16 + j] = W2[i];
    }
    for (int i = tid; i < 256; i += 32) sB1p[i] = pack2(b1[i], 0.f);
    if (tid < 16) sB2[tid] = b2[tid];
    if (tid < 16) sWI[tid] = W_init[tid];
    if (tid < 8)  sBI[tid] = b_init[tid];

    int g = tid & 3;             // k-parity (stride 4)
    int rl = tid >> 2;           // 0..7
    int rowA = blockIdx.x * 16 + rl;
    int rowB = rowA + 8;

    // prologue for both rows: mean, normalize, push-zeros-as-shift
#pragma unroll
    for (int rr = 0; rr < 2; rr++) {
        int row = rr ? rowB : rowA;
        int rib = rr ? (rl + 8) : rl;
        const float* Xr = X_in + row * LL;
        const float* Fr = fa_in + row * LL;
        int fl = fa_len[row];

        float s = 0.f;
        for (int t = g; t < LL; t += 4) s += Xr[t];
        s += __shfl_xor_sync(0xffffffffu, s, 1);
        s += __shfl_xor_sync(0xffffffffu, s, 2);
        float mean = s / (float)fl;

        int shift = LL - fl;
        int li = 2 * fl - LL - 1;
        float lastX = (li >= 0) ? (Xr[li] / mean) : 0.f;
        float lastF = Fr[fl - 1];

        for (int p = g; p < LL; p += 4) {
            float fa, xx;
            if (p < shift) { fa = lastF; xx = lastX; }
            else           { fa = Fr[p - shift]; xx = Xr[p - shift] / mean; }
            sX[rib][p] = make_float2(fa, xx);
        }
    }
    __syncwarp();

    float2 x0A = sX[rl][0];
    float2 x0B = sX[rl + 8][0];
    ull zA[4], zB[4];
#pragma unroll
    for (int j = 0; j < 4; j++) {
        float a0 = sBI[2 * j]     + sWI[4 * j]     * x0A.x + sWI[4 * j + 1] * x0A.y;
        float a1 = sBI[2 * j + 1] + sWI[4 * j + 2] * x0A.x + sWI[4 * j + 3] * x0A.y;
        zA[j] = pack2(a0, a1);
        float b0 = sBI[2 * j]     + sWI[4 * j]     * x0B.x + sWI[4 * j + 1] * x0B.y;
        float b1v = sBI[2 * j + 1] + sWI[4 * j + 2] * x0B.x + sWI[4 * j + 3] * x0B.y;
        zB[j] = pack2(b0, b1v);
    }

    float2 xaA = x0A, m0A = make_float2(0.f, 0.f), m1A;
    float2 xaB = x0B, m0B = make_float2(0.f, 0.f), m1B;
    for (int i = 0; i < LL - 1; i++) {
        float2 xbA = sX[rl][i + 1];
        float2 xbB = sX[rl + 8][i + 1];
        m1A.x = xbA.x - xaA.x;  m1A.y = xbA.y - xaA.y;
        m1B.x = xbB.x - xaB.x;  m1B.y = xbB.y - xaB.y;
        if (i == 0) { m0A = m1A; m0B = m1B; }
        substep2(zA, zB, xaA, xbA, m0A, m1A, xaB, xbB, m0B, m1B, 0.0f,
                 sW1, sW2T, sB1p, sB2, g);
        substep2(zA, zB, xaA, xbA, m0A, m1A, xaB, xbB, m0B, m1B, 0.5f,
                 sW1, sW2T, sB1p, sB2, g);
        m0A = m1A; m0B = m1B;
        xaA = xbA; xaB = xbB;
    }
    // all 4 parity lanes hold identical z; lane g writes floats [2g, 2g+1]
    {
        float a0, a1, b0, b1v;
        unpack2(zA[g], a0, a1);
        unpack2(zB[g], b0, b1v);
        g_z[rowA * 8 + 2 * g]     = a0;
        g_z[rowA * 8 + 2 * g + 1] = a1;
        g_z[rowB * 8 + 2 * g]     = b0;
        g_z[rowB * 8 + 2 * g + 1] = b1v;
    }
}

// ---------------- k2: readout MLP with smem-cached Wr2 ----------------
// 128 blocks x 256 threads. Wr2 cached in dynamic smem (rows padded to 201
// floats: bank-conflict-free for j-strided access). Each warp processes 16
// rows as 2 passes of 8 rows; h1 staged in smem as [q][r0..7].
#define K2_W2   0                    // 200*201 floats
#define K2_W1   (200 * 201)          // 1600
#define K2_B1   (K2_W1 + 1600)       // 200
#define K2_B2   (K2_B1 + 200)        // 200
#define K2_W3   (K2_B2 + 200)        // 200
#define K2_H1   (K2_W3 + 200)        // 8 warps * 1600
#define K2_SMEM_FLOATS (K2_H1 + 8 * 1600)
#define K2_SMEM_BYTES  (K2_SMEM_FLOATS * 4)

__global__ void __launch_bounds__(256, 1)
k2_readout(const float* __restrict__ Wr1, const float* __restrict__ br1,
           const float* __restrict__ Wr2, const float* __restrict__ br2,
           const float* __restrict__ Wr3, const float* __restrict__ br3) {
    extern __shared__ __align__(16) float sm[];
    int tid = threadIdx.x;
    int lane = tid & 31;
    int w = tid >> 5;

    for (int i = tid; i < 200 * 200; i += 256)
        sm[K2_W2 + (i / 200) * 201 + (i % 200)] = Wr2[i];
    for (int i = tid; i < 1600; i += 256) sm[K2_W1 + i] = Wr1[i];
    for (int i = tid; i < 200; i += 256) {
        sm[K2_B1 + i] = br1[i];
        sm[K2_B2 + i] = br2[i];
        sm[K2_W3 + i] = Wr3[i];
    }
    __syncthreads();

    float* h1w = sm + K2_H1 + w * 1600;
    float b3 = __ldg(br3);

    for (int pass = 0; pass < 2; pass++) {
        int row0 = blockIdx.x * 128 + w * 16 + pass * 8;

        // layer 1: h1[j][r] for 8 rows
        float z8[8][8];
#pragma unroll
        for (int r = 0; r < 8; r++) {
            const float4* zp = reinterpret_cast<const float4*>(g_z + (row0 + r) * 8);
            float4 u = zp[0], v = zp[1];
            z8[r][0] = u.x; z8[r][1] = u.y; z8[r][2] = u.z; z8[r][3] = u.w;
            z8[r][4] = v.x; z8[r][5] = v.y; z8[r][6] = v.z; z8[r][7] = v.w;
        }
        for (int j = lane; j < 200; j += 32) {
            const float4* wp = reinterpret_cast<const float4*>(sm + K2_W1 + j * 8);
            float4 a = wp[0], b = wp[1];
            float bj = sm[K2_B1 + j];
#pragma unroll
            for (int r = 0; r < 8; r++) {
                float h = bj;
                h = fmaf(a.x, z8[r][0], h); h = fmaf(a.y, z8[r][1], h);
                h = fmaf(a.z, z8[r][2], h); h = fmaf(a.w, z8[r][3], h);
                h = fmaf(b.x, z8[r][4], h); h = fmaf(b.y, z8[r][5], h);
                h = fmaf(b.z, z8[r][6], h); h = fmaf(b.w, z8[r][7], h);
                h1w[j * 8 + r] = h * normcdff(h);
            }
        }
        __syncwarp();

        // layer 2: 7 j's per lane (j = lane + 32u), 8 rows, f32x2 accumulators
        ull acc[7][4];
#pragma unroll
        for (int u = 0; u < 7; u++)
#pragma unroll
            for (int p = 0; p < 4; p++) acc[u][p] = 0ull;

        for (int q = 0; q < 200; q++) {
            const ull* hp = reinterpret_cast<const ull*>(h1w + q * 8);
            ull h01 = hp[0], h23 = hp[1], h45 = hp[2], h67 = hp[3];
#pragma unroll
            for (int u = 0; u < 7; u++) {
                int j = lane + 32 * u;
                float wv = (j < 200) ? sm[K2_W2 + j * 201 + q] : 0.f;
                ull w2 = pack2(wv, wv);
                acc[u][0] = fma2(w2, h01, acc[u][0]);
                acc[u][1] = fma2(w2, h23, acc[u][1]);
                acc[u][2] = fma2(w2, h45, acc[u][2]);
                acc[u][3] = fma2(w2, h67, acc[u][3]);
            }
        }

        float part[8];
#pragma unroll
        for (int r = 0; r < 8; r++) part[r] = 0.f;
#pragma unroll
        for (int u = 0; u < 7; u++) {
            int j = lane + 32 * u;
            if (j < 200) {
                float w3 = sm[K2_W3 + j];
                float b2j = sm[K2_B2 + j];
#pragma unroll
                for (int p = 0; p < 4; p++) {
                    float v0, v1; unpack2(acc[u][p], v0, v1);
                    v0 += b2j; v1 += b2j;
                    part[2 * p]     = fmaf(w3, v0 * normcdff(v0), part[2 * p]);
                    part[2 * p + 1] = fmaf(w3, v1 * normcdff(v1), part[2 * p + 1]);
                }
            }
        }
#pragma unroll
        for (int r = 0; r < 8; r++)
#pragma unroll
            for (int m = 16; m >= 1; m >>= 1)
                part[r] += __shfl_xor_sync(0xffffffffu, part[r], m);

        if (lane < 8) {
            float t = part[lane] + b3;
            float sg = 1.0f / (1.0f + expf(-t));
            g_T10[row0 + lane] = 0.1f + sg * (7.0f - 0.1f);
        }
        __syncwarp();
    }
}

__global__ void __launch_bounds__(128)
k3_out(const float* __restrict__ fa_in, const float* __restrict__ TR,
       const int* __restrict__ fa_len, float* __restrict__ out) {
    int lane = threadIdx.x & 31;
    int w = threadIdx.x >> 5;
    int row = blockIdx.x * 4 + w;

    float T10 = g_T10[row];
    float R1 = 1.0f / T10;
    float E = expf(-TR[row] * R1);
    float fa = fa_in[row * LL + lane];
    float xo = (1.0f - E) * sinf(fa) / (1.0f - cosf(fa) * E);

    float ssum = xo;
#pragma unroll
    for (int m = 16; m >= 1; m >>= 1) ssum += __shfl_xor_sync(0xffffffffu, ssum, m);

    float fl = (float)fa_len[row];
    out[row * LL + lane] = xo * fl / ssum;
    if (lane == 0) {
        out[BB * LL + row] = T10;       // T10
        out[BB * LL + BB + row] = 1.0f; // M0
    }
}

extern "C" void kernel_launch(void* const* d_in, const int* in_sizes, int n_in,
                              void* d_out, int out_size) {
    const float* X_fa_in    = (const float*)d_in[0];
    const float* fa_vals_in = (const float*)d_in[1];
    const float* TR_vals    = (const float*)d_in[2];
    const float* W_init     = (const float*)d_in[3];
    const float* b_init     = (const float*)d_in[4];
    const float* W1         = (const float*)d_in[5];
    const float* b1         = (const float*)d_in[6];
    const float* W2         = (const float*)d_in[7];
    const float* b2         = (const float*)d_in[8];
    const float* Wr1        = (const float*)d_in[9];
    const float* br1        = (const float*)d_in[10];
    const float* Wr2        = (const float*)d_in[11];
    const float* br2        = (const float*)d_in[12];
    const float* Wr3        = (const float*)d_in[13];
    const float* br3        = (const float*)d_in[14];
    // d_in[15] = fa_mask (unused)
    const int*   fa_len     = (const int*)d_in[16];

    float* out = (float*)d_out;

    // host-state op (not a stream op): capture-safe, deterministic, no alloc
    cudaFuncSetAttribute(k2_readout, cudaFuncAttributeMaxDynamicSharedMemorySize,
                         K2_SMEM_BYTES);

    k1_ode<<<BB / 16, 32>>>(X_fa_in, fa_vals_in, fa_len, W_init, b_init, W1, b1, W2, b2);
    k2_readout<<<128, 256, K2_SMEM_BYTES>>>(Wr1, br1, Wr2, br2, Wr3, br3);
    k3_out<<<BB / 4, 128>>>(fa_vals_in, TR_vals, fa_len, out);
}

// round 5
// speedup vs baseline: 1.5316x; 1.5316x over previous
#include <cuda_runtime.h>
#include <cuda_bf16.h>
#include <math.h>

#define BB 16384
#define LL 32

typedef unsigned long long ull;

// scratch (no allocation allowed)
__device__ float g_z[BB * 8];
__device__ float g_T10[BB];

__device__ __forceinline__ ull pack2(float lo, float hi) {
    ull r; asm("mov.b64 %0,{%1,%2};" : "=l"(r) : "f"(lo), "f"(hi)); return r;
}
__device__ __forceinline__ void unpack2(ull v, float& lo, float& hi) {
    asm("mov.b64 {%0,%1},%2;" : "=f"(lo), "=f"(hi) : "l"(v));
}
__device__ __forceinline__ ull fma2(ull a, ull b, ull c) {
    ull d; asm("fma.rn.f32x2 %0,%1,%2,%3;" : "=l"(d) : "l"(a), "l"(b), "l"(c)); return d;
}
__device__ __forceinline__ ull add2(ull a, ull b) {
    ull d; asm("add.rn.f32x2 %0,%1,%2;" : "=l"(d) : "l"(a), "l"(b)); return d;
}

__device__ __forceinline__ float tanh_fast(float x) {
    float e = __expf(2.0f * x);
    return 1.0f - __fdividef(2.0f, e + 1.0f);
}

__device__ __forceinline__ float2 dxval(float s, float2 x0, float2 x1, float2 m0, float2 m1) {
    float s2 = s * s;
    float cx0 = 6.f * s2 - 6.f * s;
    float cm0 = 3.f * s2 - 4.f * s + 1.f;
    float cx1 = -6.f * s2 + 6.f * s;
    float cm1 = 3.f * s2 - 2.f * s;
    float2 r;
    r.x = cx0 * x0.x + cm0 * m0.x + cx1 * x1.x + cm1 * m1.x;
    r.y = cx0 * x0.y + cm0 * m0.y + cx1 * x1.y + cm1 * m1.y;
    return r;
}

// F(s,z) for one row. Two lanes per row (g = lane&1) split k; weight loads are
// warp-broadcast. All state packed f32x2.
__device__ __forceinline__ void Feval(const ull* zp, float2 d,
                                      const float* sW1, const float* sW2T,
                                      const ull* sB1p, const float* sB2,
                                      int g, ull* kout) {
    ull a2[8];
#pragma unroll
    for (int j = 0; j < 8; j++) a2[j] = 0ull;

#pragma unroll 4
    for (int kk = g; kk < 256; kk += 2) {
        ulonglong2 w1a = *reinterpret_cast<const ulonglong2*>(sW1 + kk * 8);
        ulonglong2 w1b = *reinterpret_cast<const ulonglong2*>(sW1 + kk * 8 + 4);
        ull acc = fma2(w1a.x, zp[0], sB1p[kk]);
        acc = fma2(w1a.y, zp[1], acc);
        acc = fma2(w1b.x, zp[2], acc);
        acc = fma2(w1b.y, zp[3], acc);
        float alo, ahi; unpack2(acc, alo, ahi);
        float h = fmaxf(alo + ahi, 0.f);
        ull hh = pack2(h, h);

        ulonglong2 c0 = *reinterpret_cast<const ulonglong2*>(sW2T + kk * 16);
        ulonglong2 c1 = *reinterpret_cast<const ulonglong2*>(sW2T + kk * 16 + 4);
        ulonglong2 c2 = *reinterpret_cast<const ulonglong2*>(sW2T + kk * 16 + 8);
        ulonglong2 c3 = *reinterpret_cast<const ulonglong2*>(sW2T + kk * 16 + 12);
        a2[0] = fma2(c0.x, hh, a2[0]);
        a2[1] = fma2(c0.y, hh, a2[1]);
        a2[2] = fma2(c1.x, hh, a2[2]);
        a2[3] = fma2(c1.y, hh, a2[3]);
        a2[4] = fma2(c2.x, hh, a2[4]);
        a2[5] = fma2(c2.y, hh, a2[5]);
        a2[6] = fma2(c3.x, hh, a2[6]);
        a2[7] = fma2(c3.y, hh, a2[7]);
    }
    float av[16];
#pragma unroll
    for (int j = 0; j < 8; j++) unpack2(a2[j], av[2 * j], av[2 * j + 1]);
    // reduce across the lane pair
#pragma unroll
    for (int j = 0; j < 16; j++) av[j] += __shfl_xor_sync(0xffffffffu, av[j], 1);

#pragma unroll
    for (int hh = 0; hh < 4; hh++) {
        float g0 = tanh_fast(av[4 * hh]     + sB2[4 * hh]);
        float g1 = tanh_fast(av[4 * hh + 1] + sB2[4 * hh + 1]);
        float g2 = tanh_fast(av[4 * hh + 2] + sB2[4 * hh + 2]);
        float g3 = tanh_fast(av[4 * hh + 3] + sB2[4 * hh + 3]);
        float o0 = g0 * d.x + g1 * d.y;
        float o1 = g2 * d.x + g3 * d.y;
        kout[hh] = pack2(o0, o1);
    }
}

__device__ __forceinline__ void substep(ull* z, float2 xa, float2 xb, float2 m0, float2 m1,
                                        float s0,
                                        const float* sW1, const float* sW2T,
                                        const ull* sB1p, const float* sB2, int g) {
    float2 dA = dxval(s0,          xa, xb, m0, m1);
    float2 dB = dxval(s0 + 0.25f,  xa, xb, m0, m1);
    float2 dC = dxval(s0 + 0.5f,   xa, xb, m0, m1);

    const ull C025 = pack2(0.25f, 0.25f);
    const ull C05  = pack2(0.5f, 0.5f);
    const ull C2   = pack2(2.f, 2.f);
    const ull C112 = pack2(1.f / 12.f, 1.f / 12.f);

    ull kc[4], ks[4], zt[4];
    Feval(z, dA, sW1, sW2T, sB1p, sB2, g, kc); // k1
#pragma unroll
    for (int j = 0; j < 4; j++) { ks[j] = kc[j]; zt[j] = fma2(C025, kc[j], z[j]); }
    Feval(zt, dB, sW1, sW2T, sB1p, sB2, g, kc); // k2
#pragma unroll
    for (int j = 0; j < 4; j++) { ks[j] = fma2(C2, kc[j], ks[j]); zt[j] = fma2(C025, kc[j], z[j]); }
    Feval(zt, dB, sW1, sW2T, sB1p, sB2, g, kc); // k3
#pragma unroll
    for (int j = 0; j < 4; j++) { ks[j] = fma2(C2, kc[j], ks[j]); zt[j] = fma2(C05, kc[j], z[j]); }
    Feval(zt, dC, sW1, sW2T, sB1p, sB2, g, kc); // k4
#pragma unroll
    for (int j = 0; j < 4; j++) z[j] = fma2(C112, add2(ks[j], kc[j]), z[j]);
}

__global__ void __launch_bounds__(32, 8)
k1_ode(const float* __restrict__ X_in, const float* __restrict__ fa_in,
       const int* __restrict__ fa_len,
       const float* __restrict__ W_init, const float* __restrict__ b_init,
       const float* __restrict__ W1, const float* __restrict__ b1,
       const float* __restrict__ W2, const float* __restrict__ b2) {
    __shared__ __align__(16) float sW1[256 * 8];
    __shared__ __align__(16) float sW2T[256 * 16];
    __shared__ __align__(16) ull   sB1p[256];   // (b1, 0) packed
    __shared__ float sB2[16];
    __shared__ float sWI[16];
    __shared__ float sBI[8];
    __shared__ float2 sX[16][33];

    int tid = threadIdx.x;   // 0..31
    for (int i = tid; i < 256 * 8; i += 32) sW1[i] = W1[i];
    // W2 is (16,256); store transposed [k][j]
    for (int i = tid; i < 16 * 256; i += 32) {
        int j = i >> 8;    // 0..15
        int k = i & 255;   // 0..255
        sW2T[k * 16 + j] = W2[i];
    }
    for (int i = tid; i < 256; i += 32) sB1p[i] = pack2(b1[i], 0.f);
    if (tid < 16) sB2[tid] = b2[tid];
    if (tid < 16) sWI[tid] = W_init[tid];
    if (tid < 8)  sBI[tid] = b_init[tid];

    int g = tid & 1;             // k-parity
    int r = tid >> 1;            // row within warp, 0..15
    int row = blockIdx.x * 16 + r;

    const float* Xr = X_in + row * LL;
    const float* Fr = fa_in + row * LL;
    int fl = fa_len[row];

    float s = 0.f;
    for (int t = g; t < LL; t += 2) s += Xr[t];
    s += __shfl_xor_sync(0xffffffffu, s, 1);
    float mean = s / (float)fl;

    int shift = LL - fl;
    int li = 2 * fl - LL - 1;
    float lastX = (li >= 0) ? (Xr[li] / mean) : 0.f;
    float lastF = Fr[fl - 1];

    for (int p = g; p < LL; p += 2) {
        float fa, xx;
        if (p < shift) { fa = lastF; xx = lastX; }
        else           { fa = Fr[p - shift]; xx = Xr[p - shift] / mean; }
        sX[r][p] = make_float2(fa, xx);
    }
    __syncwarp();

    float2 x0 = sX[r][0];
    ull z[4];
#pragma unroll
    for (int j = 0; j < 4; j++) {
        float z0 = sBI[2 * j]     + sWI[4 * j]     * x0.x + sWI[4 * j + 1] * x0.y;
        float z1 = sBI[2 * j + 1] + sWI[4 * j + 2] * x0.x + sWI[4 * j + 3] * x0.y;
        z[j] = pack2(z0, z1);
    }

    float2 xa = x0, m0 = make_float2(0.f, 0.f), m1;
    for (int i = 0; i < LL - 1; i++) {
        float2 xb = sX[r][i + 1];
        m1.x = xb.x - xa.x;
        m1.y = xb.y - xa.y;
        if (i == 0) m0 = m1;
        substep(z, xa, xb, m0, m1, 0.0f, sW1, sW2T, sB1p, sB2, g);
        substep(z, xa, xb, m0, m1, 0.5f, sW1, sW2T, sB1p, sB2, g);
        m0 = m1;
        xa = xb;
    }
    // both lanes hold identical z; each writes 2 packed components
#pragma unroll
    for (int j = 0; j < 2; j++) {
        float z0, z1; unpack2(z[g * 2 + j], z0, z1);
        g_z[row * 8 + g * 4 + 2 * j]     = z0;
        g_z[row * 8 + g * 4 + 2 * j + 1] = z1;
    }
}

// ---------------- k2: readout MLP with smem-cached Wr2 ----------------
// 128 blocks x 256 threads. Wr2 cached in dynamic smem (rows padded to 201
// floats: bank-conflict-free for j-strided access). Each warp processes 16
// rows as 2 passes of 8 rows; h1 staged in smem as [q][r0..7].
#define K2_W2   0                    // 200*201 floats
#define K2_W1   (200 * 201)          // 1600
#define K2_B1   (K2_W1 + 1600)       // 200
#define K2_B2   (K2_B1 + 200)        // 200
#define K2_W3   (K2_B2 + 200)        // 200
#define K2_H1   (K2_W3 + 200)        // 8 warps * 1600
#define K2_SMEM_FLOATS (K2_H1 + 8 * 1600)
#define K2_SMEM_BYTES  (K2_SMEM_FLOATS * 4)

__global__ void __launch_bounds__(256, 1)
k2_readout(const float* __restrict__ Wr1, const float* __restrict__ br1,
           const float* __restrict__ Wr2, const float* __restrict__ br2,
           const float* __restrict__ Wr3, const float* __restrict__ br3) {
    extern __shared__ __align__(16) float sm[];
    int tid = threadIdx.x;
    int lane = tid & 31;
    int w = tid >> 5;

    for (int i = tid; i < 200 * 200; i += 256)
        sm[K2_W2 + (i / 200) * 201 + (i % 200)] = Wr2[i];
    for (int i = tid; i < 1600; i += 256) sm[K2_W1 + i] = Wr1[i];
    for (int i = tid; i < 200; i += 256) {
        sm[K2_B1 + i] = br1[i];
        sm[K2_B2 + i] = br2[i];
        sm[K2_W3 + i] = Wr3[i];
    }
    __syncthreads();

    float* h1w = sm + K2_H1 + w * 1600;
    float b3 = __ldg(br3);

    for (int pass = 0; pass < 2; pass++) {
        int row0 = blockIdx.x * 128 + w * 16 + pass * 8;

        // layer 1: h1[j][r] for 8 rows
        float z8[8][8];
#pragma unroll
        for (int r = 0; r < 8; r++) {
            const float4* zp = reinterpret_cast<const float4*>(g_z + (row0 + r) * 8);
            float4 u = zp[0], v = zp[1];
            z8[r][0] = u.x; z8[r][1] = u.y; z8[r][2] = u.z; z8[r][3] = u.w;
            z8[r][4] = v.x; z8[r][5] = v.y; z8[r][6] = v.z; z8[r][7] = v.w;
        }
        for (int j = lane; j < 200; j += 32) {
            const float4* wp = reinterpret_cast<const float4*>(sm + K2_W1 + j * 8);
            float4 a = wp[0], b = wp[1];
            float bj = sm[K2_B1 + j];
#pragma unroll
            for (int r = 0; r < 8; r++) {
                float h = bj;
                h = fmaf(a.x, z8[r][0], h); h = fmaf(a.y, z8[r][1], h);
                h = fmaf(a.z, z8[r][2], h); h = fmaf(a.w, z8[r][3], h);
                h = fmaf(b.x, z8[r][4], h); h = fmaf(b.y, z8[r][5], h);
                h = fmaf(b.z, z8[r][6], h); h = fmaf(b.w, z8[r][7], h);
                h1w[j * 8 + r] = h * normcdff(h);
            }
        }
        __syncwarp();

        // layer 2: 7 j's per lane (j = lane + 32u), 8 rows, f32x2 accumulators
        ull acc[7][4];
#pragma unroll
        for (int u = 0; u < 7; u++)
#pragma unroll
            for (int p = 0; p < 4; p++) acc[u][p] = 0ull;

        for (int q = 0; q < 200; q++) {
            const ull* hp = reinterpret_cast<const ull*>(h1w + q * 8);
            ull h01 = hp[0], h23 = hp[1], h45 = hp[2], h67 = hp[3];
#pragma unroll
            for (int u = 0; u < 7; u++) {
                int j = lane + 32 * u;
                float wv = (j < 200) ? sm[K2_W2 + j * 201 + q] : 0.f;
                ull w2 = pack2(wv, wv);
                acc[u][0] = fma2(w2, h01, acc[u][0]);
                acc[u][1] = fma2(w2, h23, acc[u][1]);
                acc[u][2] = fma2(w2, h45, acc[u][2]);
                acc[u][3] = fma2(w2, h67, acc[u][3]);
            }
        }

        float part[8];
#pragma unroll
        for (int r = 0; r < 8; r++) part[r] = 0.f;
#pragma unroll
        for (int u = 0; u < 7; u++) {
            int j = lane + 32 * u;
            if (j < 200) {
                float w3 = sm[K2_W3 + j];
                float b2j = sm[K2_B2 + j];
#pragma unroll
                for (int p = 0; p < 4; p++) {
                    float v0, v1; unpack2(acc[u][p], v0, v1);
                    v0 += b2j; v1 += b2j;
                    part[2 * p]     = fmaf(w3, v0 * normcdff(v0), part[2 * p]);
                    part[2 * p + 1] = fmaf(w3, v1 * normcdff(v1), part[2 * p + 1]);
                }
            }
        }
#pragma unroll
        for (int r = 0; r < 8; r++)
#pragma unroll
            for (int m = 16; m >= 1; m >>= 1)
                part[r] += __shfl_xor_sync(0xffffffffu, part[r], m);

        if (lane < 8) {
            float t = part[lane] + b3;
            float sg = 1.0f / (1.0f + expf(-t));
            g_T10[row0 + lane] = 0.1f + sg * (7.0f - 0.1f);
        }
        __syncwarp();
    }
}

__global__ void __launch_bounds__(128)
k3_out(const float* __restrict__ fa_in, const float* __restrict__ TR,
       const int* __restrict__ fa_len, float* __restrict__ out) {
    int lane = threadIdx.x & 31;
    int w = threadIdx.x >> 5;
    int row = blockIdx.x * 4 + w;

    float T10 = g_T10[row];
    float R1 = 1.0f / T10;
    float E = expf(-TR[row] * R1);
    float fa = fa_in[row * LL + lane];
    float xo = (1.0f - E) * sinf(fa) / (1.0f - cosf(fa) * E);

    float ssum = xo;
#pragma unroll
    for (int m = 16; m >= 1; m >>= 1) ssum += __shfl_xor_sync(0xffffffffu, ssum, m);

    float fl = (float)fa_len[row];
    out[row * LL + lane] = xo * fl / ssum;
    if (lane == 0) {
        out[BB * LL + row] = T10;       // T10
        out[BB * LL + BB + row] = 1.0f; // M0
    }
}

extern "C" void kernel_launch(void* const* d_in, const int* in_sizes, int n_in,
                              void* d_out, int out_size) {
    const float* X_fa_in    = (const float*)d_in[0];
    const float* fa_vals_in = (const float*)d_in[1];
    const float* TR_vals    = (const float*)d_in[2];
    const float* W_init     = (const float*)d_in[3];
    const float* b_init     = (const float*)d_in[4];
    const float* W1         = (const float*)d_in[5];
    const float* b1         = (const float*)d_in[6];
    const float* W2         = (const float*)d_in[7];
    const float* b2         = (const float*)d_in[8];
    const float* Wr1        = (const float*)d_in[9];
    const float* br1        = (const float*)d_in[10];
    const float* Wr2        = (const float*)d_in[11];
    const float* br2        = (const float*)d_in[12];
    const float* Wr3        = (const float*)d_in[13];
    const float* br3        = (const float*)d_in[14];
    // d_in[15] = fa_mask (unused)
    const int*   fa_len     = (const int*)d_in[16];

    float* out = (float*)d_out;

    // host-state op (not a stream op): capture-safe, deterministic, no alloc
    cudaFuncSetAttribute(k2_readout, cudaFuncAttributeMaxDynamicSharedMemorySize,
                         K2_SMEM_BYTES);

    k1_ode<<<BB / 16, 32>>>(X_fa_in, fa_vals_in, fa_len, W_init, b_init, W1, b1, W2, b2);
    k2_readout<<<128, 256, K2_SMEM_BYTES>>>(Wr1, br1, Wr2, br2, Wr3, br3);
    k3_out<<<BB / 4, 128>>>(fa_vals_in, TR_vals, fa_len, out);
}